// round 8
// baseline (speedup 1.0000x reference)
#include <cuda_runtime.h>

#define LL 8
#define KK 8
#define NN 1048576
#define NPAIR 36
#define NSLICE 37
#define NBLK (LL * NSLICE)      // 296 CTAs: 2/SM on 148 SMs, all co-resident
#define R4 (NN / 4)             // 262144 float4 per row
#define CBLK (R4 / 256)         // 1024 column-blocks of 256 float4

// Deterministic reduction scratch + barrier state (no device mallocs allowed).
__device__ float g_part[LL][NSLICE][NPAIR];
__device__ unsigned int g_bar = 0;   // monotonic ticket counter (graph-replay safe)

// ---------------------------------------------------------------------------
// Grid-wide barrier: release (fence + atomicAdd) / acquire (ld.acquire spin).
// Monotonic counter: works across unlimited graph replays (wraps after ~14M
// launches — far beyond any bench). All NBLK CTAs are co-resident by
// construction, so no deadlock.
// ---------------------------------------------------------------------------
__device__ __forceinline__ void grid_barrier() {
    __syncthreads();
    __threadfence();
    if (threadIdx.x == 0) {
        unsigned int ticket = atomicAdd(&g_bar, 1u);
        unsigned int target = (ticket / NBLK + 1u) * (unsigned int)NBLK;
        unsigned int cur;
        do {
            asm volatile("ld.global.acquire.gpu.u32 %0, [%1];"
                         : "=r"(cur) : "l"(&g_bar));
            if (cur >= target) break;
            __nanosleep(64);
        } while (true);
    }
    __syncthreads();
}

__device__ __forceinline__ void gram_accum(const float4 v[KK], float acc[NPAIR]) {
    int p = 0;
#pragma unroll
    for (int i = 0; i < KK; i++)
#pragma unroll
        for (int j = i; j < KK; j++) {
            acc[p] += v[i].x * v[j].x + v[i].y * v[j].y +
                      v[i].z * v[j].z + v[i].w * v[j].w;
            p++;
        }
}

// ---------------------------------------------------------------------------
// Fused persistent kernel.
// CTA (layer, slice) owns column-blocks c = slice + it*NSLICE (c < 1024),
// i.e. float4 positions n4 = c*256 + tid.
// Pass 1: gram partials (ascending it, pipelined, 16 LDG.128 in flight/warp).
// Barrier. Redundant per-CTA W computation (deterministic order).
// Pass 2: out over the SAME chunk, descending it (LIFO -> L2 hits on the
// pass-1 tail), two column-blocks per iteration for MLP.
// ---------------------------------------------------------------------------
__global__ __launch_bounds__(256, 2) void fused_kernel(const float* __restrict__ last,
                                                       const float* __restrict__ deltas,
                                                       const float* __restrict__ beta,
                                                       float* __restrict__ out) {
    const int bid = blockIdx.x;
    const int layer = bid % LL;
    const int slice = bid / LL;          // 0..36
    const int tid = threadIdx.x;

    const size_t off = (size_t)layer * KK * NN;
    const float4* __restrict__ d4 = reinterpret_cast<const float4*>(deltas + off);

    // iterations for this slice: c = slice + it*NSLICE < CBLK
    const int iters = (CBLK - slice + NSLICE - 1) / NSLICE;   // 28 or 27

    // ---------------- Pass 1: gram partials ----------------
    float acc[NPAIR];
#pragma unroll
    for (int p = 0; p < NPAIR; p++) acc[p] = 0.0f;

    float4 cur[KK], nxt[KK];
    {
        const int n0 = slice * 256 + tid;
#pragma unroll
        for (int j = 0; j < KK; j++) cur[j] = d4[(size_t)j * R4 + n0];
    }

    for (int it = 0; it + 1 < iters; it += 2) {
        {   // prefetch it+1
            const int n = (slice + (it + 1) * NSLICE) * 256 + tid;
#pragma unroll
            for (int j = 0; j < KK; j++) nxt[j] = d4[(size_t)j * R4 + n];
        }
        gram_accum(cur, acc);
        if (it + 2 < iters) {   // prefetch it+2
            const int n = (slice + (it + 2) * NSLICE) * 256 + tid;
#pragma unroll
            for (int j = 0; j < KK; j++) cur[j] = d4[(size_t)j * R4 + n];
        }
        gram_accum(nxt, acc);
    }
    if (iters & 1) gram_accum(cur, acc);   // last (odd) iteration, prefetched above

    // Warp reduce, then cross-warp reduce in shared (deterministic order).
#pragma unroll
    for (int p = 0; p < NPAIR; p++) {
        float a = acc[p];
#pragma unroll
        for (int o = 16; o > 0; o >>= 1)
            a += __shfl_down_sync(0xffffffffu, a, o);
        acc[p] = a;
    }
    __shared__ float s_red[8][NPAIR];
    {
        const int wid = tid >> 5, lane = tid & 31;
        if (lane == 0) {
#pragma unroll
            for (int p = 0; p < NPAIR; p++) s_red[wid][p] = acc[p];
        }
    }
    __syncthreads();
    if (tid < NPAIR) {
        float a = 0.0f;
#pragma unroll
        for (int w = 0; w < 8; w++) a += s_red[w][tid];
        g_part[layer][slice][tid] = a;
    }

    // ---------------- Barrier ----------------
    grid_barrier();

    // ---------------- W = clip(beta)*softmax(gram/sqrt(N)) + I (redundant) ----
    __shared__ float w[KK * KK];
    __shared__ float gram[NPAIR];
    if (tid < NPAIR) {
        float a = 0.0f;
        for (int s = 0; s < NSLICE; s++)
            a += __ldcg(&g_part[layer][s][tid]);
        gram[tid] = a;
    }
    __syncthreads();
    if (tid < KK) {
        const int k = tid;
        const float scale = rsqrtf((float)NN);
        float row[KK];
#pragma unroll
        for (int j = 0; j < KK; j++) {
            const int a = (k < j) ? k : j;
            const int b = (k < j) ? j : k;
            const int p = a * KK - (a * (a - 1)) / 2 + (b - a);
            row[j] = gram[p] * scale;
        }
        float m = row[0];
#pragma unroll
        for (int j = 1; j < KK; j++) m = fmaxf(m, row[j]);
        float sm = 0.0f;
#pragma unroll
        for (int j = 0; j < KK; j++) { row[j] = expf(row[j] - m); sm += row[j]; }
        const float inv = 1.0f / sm;
        float b = beta[layer * KK + k];
        b = fminf(fmaxf(b, 0.0f), 1.0f);
#pragma unroll
        for (int j = 0; j < KK; j++)
            w[k * KK + j] = b * row[j] * inv + ((j == k) ? 1.0f : 0.0f);
    }
    __syncthreads();

    // ---------------- Pass 2: out, descending (LIFO L2 harvest), pairs -------
    const float4* __restrict__ l4 = reinterpret_cast<const float4*>(last + off);
    float4* __restrict__ o4 = reinterpret_cast<float4*>(out + off);

    int it = iters - 1;
    for (; it >= 1; it -= 2) {
        const int na = (slice + it * NSLICE) * 256 + tid;
        const int nb = (slice + (it - 1) * NSLICE) * 256 + tid;
        float4 da[KK], db[KK];
#pragma unroll
        for (int j = 0; j < KK; j++) da[j] = d4[(size_t)j * R4 + na];
#pragma unroll
        for (int j = 0; j < KK; j++) db[j] = d4[(size_t)j * R4 + nb];

#pragma unroll
        for (int k = 0; k < KK; k++) {
            float4 aa = l4[(size_t)k * R4 + na];
            float4 ab = l4[(size_t)k * R4 + nb];
#pragma unroll
            for (int j = 0; j < KK; j++) {
                const float wv = w[k * KK + j];
                aa.x = fmaf(wv, da[j].x, aa.x);
                aa.y = fmaf(wv, da[j].y, aa.y);
                aa.z = fmaf(wv, da[j].z, aa.z);
                aa.w = fmaf(wv, da[j].w, aa.w);
                ab.x = fmaf(wv, db[j].x, ab.x);
                ab.y = fmaf(wv, db[j].y, ab.y);
                ab.z = fmaf(wv, db[j].z, ab.z);
                ab.w = fmaf(wv, db[j].w, ab.w);
            }
            o4[(size_t)k * R4 + na] = aa;
            o4[(size_t)k * R4 + nb] = ab;
        }
    }
    if (it == 0) {   // odd iters: final single column-block
        const int n = slice * 256 + tid;
        float4 d[KK];
#pragma unroll
        for (int j = 0; j < KK; j++) d[j] = d4[(size_t)j * R4 + n];
#pragma unroll
        for (int k = 0; k < KK; k++) {
            float4 a2 = l4[(size_t)k * R4 + n];
#pragma unroll
            for (int j = 0; j < KK; j++) {
                const float wv = w[k * KK + j];
                a2.x = fmaf(wv, d[j].x, a2.x);
                a2.y = fmaf(wv, d[j].y, a2.y);
                a2.z = fmaf(wv, d[j].z, a2.z);
                a2.w = fmaf(wv, d[j].w, a2.w);
            }
            o4[(size_t)k * R4 + n] = a2;
        }
    }
}

extern "C" void kernel_launch(void* const* d_in, const int* in_sizes, int n_in,
                              void* d_out, int out_size) {
    const float* last   = (const float*)d_in[0];
    const float* deltas = (const float*)d_in[1];
    const float* beta   = (const float*)d_in[2];
    float* out = (float*)d_out;

    fused_kernel<<<NBLK, 256>>>(last, deltas, beta, out);
}

// round 9
// speedup vs baseline: 1.3603x; 1.3603x over previous
#include <cuda_runtime.h>

#define LL 8
#define KK 8
#define NN 1048576
#define GBLK 128            // gram blocks per layer
#define OBLK 256            // output blocks per layer
#define NPAIR 36            // upper-triangular 8x8 pairs

// Deterministic reduction scratch (no device mallocs allowed).
__device__ float g_part[LL][GBLK][NPAIR];
__device__ float g_w[LL][KK * KK];

// ---------------------------------------------------------------------------
// Kernel 1: per-block partial Gram sums (upper triangle incl. diagonal).
// float4 loads + 2-stage software pipeline: 16 outstanding LDG.128 per warp
// (8KB/warp, 128KB/SM at 2 CTAs) — best measured variant (47.9us, 5.7TB/s).
// grid = (GBLK, LL), block = 256.
// ---------------------------------------------------------------------------
__global__ __launch_bounds__(256, 2) void gram_kernel(const float* __restrict__ deltas) {
    const int layer = blockIdx.y;
    const float4* __restrict__ base =
        reinterpret_cast<const float4*>(deltas + (size_t)layer * KK * NN);
    const int tid = threadIdx.x;

    float acc[NPAIR];
#pragma unroll
    for (int p = 0; p < NPAIR; p++) acc[p] = 0.0f;

    const int R4 = NN / 4;                // float4 per row = 262144
    const int stride = GBLK * 256;        // 32768 float4 per sweep
    const int iters = R4 / stride;        // 8 (even)
    const int n0 = blockIdx.x * 256 + tid;

    float4 cur[KK], nxt[KK];
#pragma unroll
    for (int j = 0; j < KK; j++) cur[j] = base[(size_t)j * R4 + n0];

    for (int it = 0; it < iters; it += 2) {
        // prefetch it+1 (always valid: iters even)
        {
            const int n = n0 + (it + 1) * stride;
#pragma unroll
            for (int j = 0; j < KK; j++) nxt[j] = base[(size_t)j * R4 + n];
        }
        // compute on cur
        {
            int p = 0;
#pragma unroll
            for (int i = 0; i < KK; i++)
#pragma unroll
                for (int j = i; j < KK; j++) {
                    acc[p] += cur[i].x * cur[j].x + cur[i].y * cur[j].y +
                              cur[i].z * cur[j].z + cur[i].w * cur[j].w;
                    p++;
                }
        }
        // prefetch it+2 into cur (guarded)
        if (it + 2 < iters) {
            const int n = n0 + (it + 2) * stride;
#pragma unroll
            for (int j = 0; j < KK; j++) cur[j] = base[(size_t)j * R4 + n];
        }
        // compute on nxt
        {
            int p = 0;
#pragma unroll
            for (int i = 0; i < KK; i++)
#pragma unroll
                for (int j = i; j < KK; j++) {
                    acc[p] += nxt[i].x * nxt[j].x + nxt[i].y * nxt[j].y +
                              nxt[i].z * nxt[j].z + nxt[i].w * nxt[j].w;
                    p++;
                }
        }
    }

    // Warp-level reduce each of the 36 accumulators.
#pragma unroll
    for (int p = 0; p < NPAIR; p++) {
        float a = acc[p];
#pragma unroll
        for (int o = 16; o > 0; o >>= 1)
            a += __shfl_down_sync(0xffffffffu, a, o);
        acc[p] = a;
    }

    __shared__ float s[8][NPAIR];
    const int wid = tid >> 5, lane = tid & 31;
    if (lane == 0) {
#pragma unroll
        for (int p = 0; p < NPAIR; p++) s[wid][p] = acc[p];
    }
    __syncthreads();

    if (tid < NPAIR) {
        float a = 0.0f;
#pragma unroll
        for (int w = 0; w < 8; w++) a += s[w][tid];
        g_part[layer][blockIdx.x][tid] = a;
    }
}

// ---------------------------------------------------------------------------
// Kernel 2: reduce partials -> logits -> softmax -> W = clip(beta)*attn + I.
// grid = LL, block = 64. Tiny.
// ---------------------------------------------------------------------------
__global__ __launch_bounds__(64) void finish_kernel(const float* __restrict__ beta) {
    const int layer = blockIdx.x;
    const int tid = threadIdx.x;
    __shared__ float gram[NPAIR];

    if (tid < NPAIR) {
        float a = 0.0f;
        for (int b = 0; b < GBLK; b++) a += g_part[layer][b][tid];
        gram[tid] = a;
    }
    __syncthreads();

    if (tid < KK) {
        const int k = tid;
        const float scale = rsqrtf((float)NN);   // N^-0.5
        float row[KK];
#pragma unroll
        for (int j = 0; j < KK; j++) {
            const int a = (k < j) ? k : j;
            const int b = (k < j) ? j : k;
            const int p = a * KK - (a * (a - 1)) / 2 + (b - a);
            row[j] = gram[p] * scale;
        }
        float m = row[0];
#pragma unroll
        for (int j = 1; j < KK; j++) m = fmaxf(m, row[j]);
        float s = 0.0f;
#pragma unroll
        for (int j = 0; j < KK; j++) { row[j] = expf(row[j] - m); s += row[j]; }
        const float inv = 1.0f / s;
        float b = beta[layer * KK + k];
        b = fminf(fmaxf(b, 0.0f), 1.0f);
#pragma unroll
        for (int j = 0; j < KK; j++)
            g_w[layer][k * KK + j] = b * row[j] * inv + ((j == k) ? 1.0f : 0.0f);
    }
}

// ---------------------------------------------------------------------------
// Kernel 3: out[l,k,n] = last[l,k,n] + sum_j W[l,k,j] * deltas[l,j,n]
// Batched-load version: ALL 16 LDG.128 (8 deltas + 8 last) issued before any
// FMA, accumulate in place into the last-regs, then 8 stores. 8KB outstanding
// loads/warp, 2 CTAs/SM -> 128KB/SM in flight (best measured config on gram).
// Descending chunk order kept (small measured win in R7).
// grid = (OBLK, LL), block = 256.
// ---------------------------------------------------------------------------
__global__ __launch_bounds__(256, 2) void out_kernel(const float* __restrict__ last,
                                                     const float* __restrict__ deltas,
                                                     float* __restrict__ out) {
    const int layer = blockIdx.y;
    __shared__ float w[KK * KK];
    const int tid = threadIdx.x;
    if (tid < KK * KK) w[tid] = g_w[layer][tid];
    __syncthreads();

    const size_t off = (size_t)layer * KK * NN;
    const float4* __restrict__ d4 = reinterpret_cast<const float4*>(deltas + off);
    const float4* __restrict__ l4 = reinterpret_cast<const float4*>(last + off);
    float4* __restrict__ o4 = reinterpret_cast<float4*>(out + off);

    const int R = NN / 4;                 // 262144
    const int stride = OBLK * 256;        // 65536
    const int iters = R / stride;         // 4
    const int idx = blockIdx.x * 256 + tid;

#pragma unroll
    for (int it = iters - 1; it >= 0; it--) {   // descending chunks
        const int n4 = idx + it * stride;

        float4 d[KK];
        float4 a[KK];
#pragma unroll
        for (int j = 0; j < KK; j++)
            d[j] = d4[(size_t)j * R + n4];
#pragma unroll
        for (int k = 0; k < KK; k++)
            a[k] = l4[(size_t)k * R + n4];

#pragma unroll
        for (int k = 0; k < KK; k++) {
#pragma unroll
            for (int j = 0; j < KK; j++) {
                const float wv = w[k * KK + j];
                a[k].x = fmaf(wv, d[j].x, a[k].x);
                a[k].y = fmaf(wv, d[j].y, a[k].y);
                a[k].z = fmaf(wv, d[j].z, a[k].z);
                a[k].w = fmaf(wv, d[j].w, a[k].w);
            }
        }

#pragma unroll
        for (int k = 0; k < KK; k++)
            o4[(size_t)k * R + n4] = a[k];
    }
}

extern "C" void kernel_launch(void* const* d_in, const int* in_sizes, int n_in,
                              void* d_out, int out_size) {
    const float* last   = (const float*)d_in[0];
    const float* deltas = (const float*)d_in[1];
    const float* beta   = (const float*)d_in[2];
    float* out = (float*)d_out;

    dim3 ggrid(GBLK, LL);
    gram_kernel<<<ggrid, 256>>>(deltas);

    finish_kernel<<<LL, 64>>>(beta);

    dim3 ogrid(OBLK, LL);
    out_kernel<<<ogrid, 256>>>(last, deltas, out);
}